// round 12
// baseline (speedup 1.0000x reference)
#include <cuda_runtime.h>
#include <cstdint>
#include <cstddef>

#define NB   32
#define NFR  16
#define NT   192
#define DD   256
#define NS   21
#define BSROWS (NB*NS)          // 672
#define SM_SCALE 0.0625f
#define ATT_EPS 1e-8f
#define LN_EPS  1e-5f

// ---------------- scratch (device globals; no allocation) ----------------
static __device__ float g_k[(size_t)NB*NFR*NT*DD];
static __device__ float g_v[(size_t)NB*NFR*NT*DD];
static __device__ float g_slots[BSROWS*DD];
static __device__ float g_q[BSROWS*DD];
static __device__ float g_upd[BSROWS*DD];
static __device__ float g_gi[(size_t)BSROWS*3*DD];
static __device__ float g_gh[(size_t)BSROWS*3*DD];
static __device__ float g_h[BSROWS*DD];
static __device__ float g_t[BSROWS*DD];

// ---------------- cluster barrier (4 CTAs, HW) ----------------------------
__device__ __forceinline__ void csync() {
    __syncthreads();
    __threadfence();
    asm volatile("barrier.cluster.arrive.aligned;" ::: "memory");
    asm volatile("barrier.cluster.wait.aligned;"   ::: "memory");
}

// ---------------- shared memory union -------------------------------------
struct GemmSm {
    float As[32][24];       // A^T tile: [k][row], 21 rows used
    float Ws[32][68];       // W^T tile: [k][col], up to 64 cols
    float mean[NS], rstd[NS];
    float red[NS][8][2];
    float dt[NS][52];
};
struct UpdSm {
    float a_s[NS*NT];
    float rsum[NS];
    float red[4][NS][64];
};
union SmemAll {
    GemmSm g;
    UpdSm  u;
};

// ---------------- 21x64 GEMM tile, K=256 ----------------------------------
// C[0:21, col0:col0+64] = epi( LN?(A) @ W^T + bias ).  A: 21 x 256 (stride 256).
// 256 threads; warps 0..6 compute (3 rows x 2 cols per thread).
template<bool LN, int EPI>
__device__ void gemm64(SmemAll* smp,
                       const float* __restrict__ A,
                       const float* __restrict__ W,
                       const float* __restrict__ bias,
                       float* __restrict__ C, int ldc, int col0,
                       const float* __restrict__ gamma,
                       const float* __restrict__ beta,
                       const float* __restrict__ R)
{
    GemmSm& s = smp->g;
    const int tid = threadIdx.x;

    if (LN) {
        if (tid < 168) {
            int r = tid >> 3, p = tid & 7;              // 21 rows x 8 partials
            const float4* ap = reinterpret_cast<const float4*>(A + r * DD + p * 32);
            float ss = 0.f, ss2 = 0.f;
            #pragma unroll
            for (int u = 0; u < 8; ++u) {
                float4 x = ap[u];
                ss  += x.x + x.y + x.z + x.w;
                ss2 += x.x*x.x + x.y*x.y + x.z*x.z + x.w*x.w;
            }
            s.red[r][p][0] = ss; s.red[r][p][1] = ss2;
        }
        __syncthreads();
        if (tid < NS) {
            float a0 = 0.f, a1 = 0.f;
            #pragma unroll
            for (int p = 0; p < 8; ++p) { a0 += s.red[tid][p][0]; a1 += s.red[tid][p][1]; }
            float m = a0 * (1.0f/DD);
            s.mean[tid] = m;
            s.rstd[tid] = rsqrtf(a1*(1.0f/DD) - m*m + LN_EPS);
        }
        __syncthreads();
    }

    float acc[3][2] = {};
    const int g  = tid >> 5;            // warp id 0..7 (0..6 compute)
    const int cc = (tid & 31) << 1;     // col pair 0..62

    for (int kk = 0; kk < DD; kk += 32) {
        if (tid < 168) {                // A tile 21x32 -> transposed
            int i = tid >> 3, kq = (tid & 7) << 2;
            float4 v = *reinterpret_cast<const float4*>(A + i * DD + kk + kq);
            if (LN) {
                float m = s.mean[i], rs = s.rstd[i];
                float4 gg = *reinterpret_cast<const float4*>(gamma + kk + kq);
                float4 bb = *reinterpret_cast<const float4*>(beta  + kk + kq);
                v.x = (v.x - m)*rs*gg.x + bb.x;
                v.y = (v.y - m)*rs*gg.y + bb.y;
                v.z = (v.z - m)*rs*gg.z + bb.z;
                v.w = (v.w - m)*rs*gg.w + bb.w;
            }
            s.As[kq+0][i]=v.x; s.As[kq+1][i]=v.y; s.As[kq+2][i]=v.z; s.As[kq+3][i]=v.w;
        }
        #pragma unroll
        for (int l = 0; l < 2; ++l) {   // W tile 64x32: 512 float4 / 256 thr
            int t = tid + l * 256;
            int j = t >> 3, kq = (t & 7) << 2;
            float4 v = *reinterpret_cast<const float4*>(W + (size_t)(col0 + j) * DD + kk + kq);
            s.Ws[kq+0][j]=v.x; s.Ws[kq+1][j]=v.y; s.Ws[kq+2][j]=v.z; s.Ws[kq+3][j]=v.w;
        }
        __syncthreads();
        if (g < 7) {
            #pragma unroll
            for (int k = 0; k < 32; ++k) {
                float a0 = s.As[k][3*g+0];
                float a1 = s.As[k][3*g+1];
                float a2 = s.As[k][3*g+2];
                float2 b2 = *reinterpret_cast<const float2*>(&s.Ws[k][cc]);
                acc[0][0] += a0*b2.x; acc[0][1] += a0*b2.y;
                acc[1][0] += a1*b2.x; acc[1][1] += a1*b2.y;
                acc[2][0] += a2*b2.x; acc[2][1] += a2*b2.y;
            }
        }
        __syncthreads();
    }

    if (g < 7) {
        float2 bb = *reinterpret_cast<const float2*>(bias + col0 + cc);
        #pragma unroll
        for (int ii = 0; ii < 3; ++ii) {
            int r = 3*g + ii;
            float2 o;
            o.x = acc[ii][0] + bb.x;
            o.y = acc[ii][1] + bb.y;
            if (EPI == 1) { o.x = fmaxf(o.x, 0.f); o.y = fmaxf(o.y, 0.f); }
            if (EPI == 2) {
                float2 rr = *reinterpret_cast<const float2*>(R + r * DD + col0 + cc);
                o.x += rr.x; o.y += rr.y;
            }
            *reinterpret_cast<float2*>(C + (size_t)r * ldc + col0 + cc) = o;
        }
    }
}

// ---------------- attn: dots(21x48) + col-softmax(+eps) -------------------
__device__ void attn48(SmemAll* smp,
                       const float* __restrict__ qb,     // 21 x 256
                       const float* __restrict__ kf,     // frame base: 192 x 256
                       float* __restrict__ out_bf,       // 21 x 192
                       int j0)
{
    GemmSm& s = smp->g;
    const int tid = threadIdx.x;
    const int g  = tid >> 5;
    const int cl = tid & 31;
    const int cc = cl << 1;
    float acc[3][2] = {};

    for (int kk = 0; kk < DD; kk += 32) {
        if (tid < 168) {
            int i = tid >> 3, kq = (tid & 7) << 2;
            float4 v = *reinterpret_cast<const float4*>(qb + i * DD + kk + kq);
            s.As[kq+0][i]=v.x; s.As[kq+1][i]=v.y; s.As[kq+2][i]=v.z; s.As[kq+3][i]=v.w;
        }
        #pragma unroll
        for (int l = 0; l < 2; ++l) {   // K tile 48x32: 384 float4
            int t = tid + l * 256;
            if (t < 384) {
                int j = t >> 3, kq = (t & 7) << 2;
                float4 v = *reinterpret_cast<const float4*>(kf + (size_t)(j0 + j) * DD + kk + kq);
                s.Ws[kq+0][j]=v.x; s.Ws[kq+1][j]=v.y; s.Ws[kq+2][j]=v.z; s.Ws[kq+3][j]=v.w;
            }
        }
        __syncthreads();
        if (g < 7 && cl < 24) {
            #pragma unroll
            for (int k = 0; k < 32; ++k) {
                float a0 = s.As[k][3*g+0];
                float a1 = s.As[k][3*g+1];
                float a2 = s.As[k][3*g+2];
                float2 b2 = *reinterpret_cast<const float2*>(&s.Ws[k][cc]);
                acc[0][0] += a0*b2.x; acc[0][1] += a0*b2.y;
                acc[1][0] += a1*b2.x; acc[1][1] += a1*b2.y;
                acc[2][0] += a2*b2.x; acc[2][1] += a2*b2.y;
            }
        }
        __syncthreads();
    }
    if (g < 7 && cl < 24) {
        #pragma unroll
        for (int ii = 0; ii < 3; ++ii) {
            s.dt[3*g+ii][cc+0] = acc[ii][0]*SM_SCALE;
            s.dt[3*g+ii][cc+1] = acc[ii][1]*SM_SCALE;
        }
    }
    __syncthreads();
    if (tid < 48) {
        int j = tid;
        float m = -1e30f;
        #pragma unroll
        for (int i = 0; i < NS; ++i) m = fmaxf(m, s.dt[i][j]);
        float e[NS]; float sum = 0.f;
        #pragma unroll
        for (int i = 0; i < NS; ++i) { e[i] = __expf(s.dt[i][j] - m); sum += e[i]; }
        float inv = 1.0f / sum;
        #pragma unroll
        for (int i = 0; i < NS; ++i) out_bf[(size_t)i * NT + j0 + j] = e[i]*inv + ATT_EPS;
    }
    __syncthreads();
}

// ---------------- updates tile = (attn @ v) / rowsum(attn) ----------------
__device__ void upd_tile(SmemAll* sm,
                         const float* __restrict__ attn,
                         const float* __restrict__ vall,
                         float* __restrict__ upd,
                         int f, int b, int d0)
{
    UpdSm& s = sm->u;
    const int tid = threadIdx.x;
    const float* ab = attn + (size_t)(b*NFR + f) * NS * NT;
    const float4* ab4 = reinterpret_cast<const float4*>(ab);
    float4* as4 = reinterpret_cast<float4*>(s.a_s);
    for (int t = tid; t < NS*NT/4; t += 256) as4[t] = ab4[t];
    __syncthreads();
    if (tid < NS) {
        float sum = 0.f;
        const float* row = &s.a_s[tid * NT];
        for (int j = 0; j < NT; ++j) sum += row[j];
        s.rsum[tid] = 1.0f / sum;
    }
    int jg = tid >> 6, dl = tid & 63;
    const float* vb = vall + ((size_t)(b*NFR + f) * NT) * DD + d0 + dl;
    float acc[NS] = {};
    int jbase = jg * 48;
    for (int j4 = 0; j4 < 48; j4 += 4) {
        float v0 = vb[(size_t)(jbase + j4 + 0) * DD];
        float v1 = vb[(size_t)(jbase + j4 + 1) * DD];
        float v2 = vb[(size_t)(jbase + j4 + 2) * DD];
        float v3 = vb[(size_t)(jbase + j4 + 3) * DD];
        #pragma unroll
        for (int i = 0; i < NS; ++i) {
            float4 a = *reinterpret_cast<const float4*>(&s.a_s[i*NT + jbase + j4]);
            acc[i] += a.x*v0 + a.y*v1 + a.z*v2 + a.w*v3;
        }
    }
    #pragma unroll
    for (int i = 0; i < NS; ++i) s.red[jg][i][dl] = acc[i];
    __syncthreads();
    if (tid < 64) {
        #pragma unroll
        for (int i = 0; i < NS; ++i) {
            float sum = s.red[0][i][tid] + s.red[1][i][tid] + s.red[2][i][tid] + s.red[3][i][tid];
            upd[((size_t)b*NS + i) * DD + d0 + tid] = sum * s.rsum[i];
        }
    }
    __syncthreads();
}

// ---------------- persistent per-batch cluster kernel ---------------------
__global__ void __launch_bounds__(256, 1) __cluster_dims__(4, 1, 1)
persist_kernel(const float* __restrict__ noise,
               const float* __restrict__ mu,
               const float* __restrict__ sg,
               const float* __restrict__ Wq, const float* __restrict__ bq,
               const float* __restrict__ W1, const float* __restrict__ b1,
               const float* __restrict__ W2, const float* __restrict__ b2,
               const float* __restrict__ W_ih, const float* __restrict__ b_ih,
               const float* __restrict__ W_hh, const float* __restrict__ b_hh,
               const float* __restrict__ g_sl, const float* __restrict__ be_sl,
               const float* __restrict__ g_ff, const float* __restrict__ be_ff,
               float* __restrict__ out_slots,
               float* __restrict__ out_attn)
{
    __shared__ SmemAll sm;
    const int tid = threadIdx.x;
    const int b = blockIdx.x >> 2;      // batch = cluster id
    const int c = blockIdx.x & 3;       // rank within cluster

    float* slots_b = g_slots + b * NS * DD;
    float* q_b     = g_q     + b * NS * DD;
    float* upd_b   = g_upd   + b * NS * DD;
    float* h_b     = g_h     + b * NS * DD;
    float* t_b     = g_t     + b * NS * DD;
    float* gh_b    = g_gh    + (size_t)b * NS * 3 * DD;
    float* gi_b    = g_gi    + (size_t)b * NS * 3 * DD;

    // init slots0 = mu + sigma*noise (this batch; each CTA a quarter)
    {
        const float4* mu4 = reinterpret_cast<const float4*>(mu);
        const float4* sg4 = reinterpret_cast<const float4*>(sg);
        const float4* nz4 = reinterpret_cast<const float4*>(noise + b * NS * DD);
        float4* sl4 = reinterpret_cast<float4*>(slots_b);
        for (int t4 = c*336 + tid; t4 < (c+1)*336; t4 += 256) {
            int d4 = t4 & 63;
            float4 m = mu4[d4], s4 = sg4[d4], n4 = nz4[t4];
            float4 o;
            o.x = m.x + s4.x*n4.x; o.y = m.y + s4.y*n4.y;
            o.z = m.z + s4.z*n4.z; o.w = m.w + s4.w*n4.w;
            sl4[t4] = o;
        }
    }
    csync();

    for (int f = 0; f < NFR; ++f) {
        const float* kf = g_k + (size_t)(b*NFR + f) * NT * DD;
        float* attn_bf  = out_attn + (size_t)(b*NFR + f) * NS * NT;
        for (int it = 0; it < 3; ++it) {
            // ---- P1: q = LN(slots)@Wq^T (4 tiles) ; gh = slots@W_hh^T (12 tiles)
            #pragma unroll 1
            for (int tt = 0; tt < 4; ++tt) {
                int id = c + tt*4;
                if (id < 4)
                    gemm64<true, 0>(&sm, slots_b, Wq, bq, q_b, DD, id*64,
                                    g_sl, be_sl, nullptr);
                else
                    gemm64<false, 0>(&sm, slots_b, W_hh, b_hh, gh_b, 3*DD, (id-4)*64,
                                     nullptr, nullptr, nullptr);
            }
            csync();
            // ---- P2: dots + softmax(+eps), 48 cols per CTA
            attn48(&sm, q_b, kf, attn_bf, c*48);
            csync();
            // ---- P3: updates, 64 d-cols per CTA
            upd_tile(&sm, out_attn, g_v, g_upd, f, b, c*64);
            csync();
            // ---- P4: gi = upd@W_ih^T (12 tiles, 3 per CTA)
            #pragma unroll 1
            for (int tt = 0; tt < 3; ++tt) {
                int id = c + tt*4;
                gemm64<false, 0>(&sm, upd_b, W_ih, b_ih, gi_b, 3*DD, id*64,
                                 nullptr, nullptr, nullptr);
            }
            csync();
            // ---- P5: GRU pointwise -> h (64 d-cols per CTA)
            {
                int d0 = c * 64;
                for (int t = tid; t < NS*16; t += 256) {
                    int row = t >> 4;
                    int dq = (t & 15) << 2;
                    size_t gb = (size_t)row * 3*DD + d0 + dq;
                    float4 ir = *reinterpret_cast<const float4*>(gi_b + gb);
                    float4 iz = *reinterpret_cast<const float4*>(gi_b + gb + DD);
                    float4 in = *reinterpret_cast<const float4*>(gi_b + gb + 2*DD);
                    float4 hr = *reinterpret_cast<const float4*>(gh_b + gb);
                    float4 hz = *reinterpret_cast<const float4*>(gh_b + gb + DD);
                    float4 hn = *reinterpret_cast<const float4*>(gh_b + gb + 2*DD);
                    float4 hv = *reinterpret_cast<const float4*>(slots_b + (size_t)row*DD + d0 + dq);
                    float4 o;
                    float r0 = 1.0f/(1.0f+__expf(-(ir.x+hr.x)));
                    float z0 = 1.0f/(1.0f+__expf(-(iz.x+hz.x)));
                    float n0 = tanhf(in.x + r0*hn.x);
                    o.x = (1.0f - z0)*n0 + z0*hv.x;
                    float r1 = 1.0f/(1.0f+__expf(-(ir.y+hr.y)));
                    float z1 = 1.0f/(1.0f+__expf(-(iz.y+hz.y)));
                    float n1 = tanhf(in.y + r1*hn.y);
                    o.y = (1.0f - z1)*n1 + z1*hv.y;
                    float r2 = 1.0f/(1.0f+__expf(-(ir.z+hr.z)));
                    float z2 = 1.0f/(1.0f+__expf(-(iz.z+hz.z)));
                    float n2 = tanhf(in.z + r2*hn.z);
                    o.z = (1.0f - z2)*n2 + z2*hv.z;
                    float r3 = 1.0f/(1.0f+__expf(-(ir.w+hr.w)));
                    float z3 = 1.0f/(1.0f+__expf(-(iz.w+hz.w)));
                    float n3 = tanhf(in.w + r3*hn.w);
                    o.w = (1.0f - z3)*n3 + z3*hv.w;
                    *reinterpret_cast<float4*>(h_b + (size_t)row*DD + d0 + dq) = o;
                }
            }
            csync();
            // ---- P6: t = relu(LN(h)@W1^T + b1), 1 tile per CTA
            gemm64<true, 1>(&sm, h_b, W1, b1, t_b, DD, c*64, g_ff, be_ff, nullptr);
            csync();
            // ---- P7: slots = h + t@W2^T + b2, 1 tile per CTA
            gemm64<false, 2>(&sm, t_b, W2, b2, slots_b, DD, c*64, nullptr, nullptr, h_b);
            csync();
        }
    }

    // final: out_slots[b, 0:20, :] — each CTA writes its 64-col chunk
    {
        const float4* sl4 = reinterpret_cast<const float4*>(slots_b);
        float4* o4 = reinterpret_cast<float4*>(out_slots + (size_t)b * 20 * DD);
        for (int t = tid; t < 20*16; t += 256) {
            int row = t >> 4;
            int dq = t & 15;
            o4[row*64 + c*16 + dq] = sl4[row*64 + c*16 + dq];
        }
    }
}

// ---------------- kv projection GEMM: 128x128 tiles (R11-proven) ----------
__global__ void __launch_bounds__(256)
kv_gemm(const float* __restrict__ A,
        const float* __restrict__ W,
        const float* __restrict__ bias,
        float* __restrict__ C,
        const float* __restrict__ gamma,
        const float* __restrict__ beta)
{
    __shared__ float As[32][132];
    __shared__ float Ws[32][132];
    __shared__ float s_mean[128], s_rstd[128];
    __shared__ float s_red[128][2][2];

    const int tid  = threadIdx.x;
    const int row0 = blockIdx.y * 128;
    const int col0 = blockIdx.x * 128;

    {
        int r = tid >> 1, p = tid & 1;
        const float4* ap = reinterpret_cast<const float4*>(A + (size_t)(row0 + r) * DD + p * 128);
        float s = 0.f, s2 = 0.f;
        #pragma unroll
        for (int u = 0; u < 32; ++u) {
            float4 x = ap[u];
            s  += x.x + x.y + x.z + x.w;
            s2 += x.x*x.x + x.y*x.y + x.z*x.z + x.w*x.w;
        }
        s_red[r][p][0] = s; s_red[r][p][1] = s2;
        __syncthreads();
        if (tid < 128) {
            float ss  = s_red[tid][0][0] + s_red[tid][1][0];
            float ss2 = s_red[tid][0][1] + s_red[tid][1][1];
            float m = ss * (1.0f/DD);
            s_mean[tid] = m;
            s_rstd[tid] = rsqrtf(ss2*(1.0f/DD) - m*m + LN_EPS);
        }
        __syncthreads();
    }

    float acc[8][8] = {};
    const int ty = tid >> 4;
    const int tx = tid & 15;

    for (int kk = 0; kk < DD; kk += 32) {
        #pragma unroll
        for (int l = 0; l < 4; ++l) {
            int t = tid + l * 256;
            int i = t >> 3, kq = (t & 7) << 2;
            float4 v = *reinterpret_cast<const float4*>(A + (size_t)(row0 + i) * DD + kk + kq);
            float m = s_mean[i], rs = s_rstd[i];
            float4 g  = *reinterpret_cast<const float4*>(gamma + kk + kq);
            float4 bb = *reinterpret_cast<const float4*>(beta  + kk + kq);
            v.x = (v.x - m)*rs*g.x + bb.x;
            v.y = (v.y - m)*rs*g.y + bb.y;
            v.z = (v.z - m)*rs*g.z + bb.z;
            v.w = (v.w - m)*rs*g.w + bb.w;
            As[kq+0][i]=v.x; As[kq+1][i]=v.y; As[kq+2][i]=v.z; As[kq+3][i]=v.w;
        }
        #pragma unroll
        for (int l = 0; l < 4; ++l) {
            int t = tid + l * 256;
            int j = t >> 3, kq = (t & 7) << 2;
            float4 v = *reinterpret_cast<const float4*>(W + (size_t)(col0 + j) * DD + kk + kq);
            Ws[kq+0][j]=v.x; Ws[kq+1][j]=v.y; Ws[kq+2][j]=v.z; Ws[kq+3][j]=v.w;
        }
        __syncthreads();
        #pragma unroll
        for (int k = 0; k < 32; ++k) {
            float4 a0 = *reinterpret_cast<const float4*>(&As[k][ty<<2]);
            float4 a1 = *reinterpret_cast<const float4*>(&As[k][64 + (ty<<2)]);
            float4 b0 = *reinterpret_cast<const float4*>(&Ws[k][tx<<2]);
            float4 b1 = *reinterpret_cast<const float4*>(&Ws[k][64 + (tx<<2)]);
            float av[8] = {a0.x,a0.y,a0.z,a0.w, a1.x,a1.y,a1.z,a1.w};
            float bv[8] = {b0.x,b0.y,b0.z,b0.w, b1.x,b1.y,b1.z,b1.w};
            #pragma unroll
            for (int i = 0; i < 8; ++i)
                #pragma unroll
                for (int j = 0; j < 8; ++j)
                    acc[i][j] += av[i] * bv[j];
        }
        __syncthreads();
    }

    float4 bb0 = *reinterpret_cast<const float4*>(bias + col0 + (tx<<2));
    float4 bb1 = *reinterpret_cast<const float4*>(bias + col0 + 64 + (tx<<2));
    #pragma unroll
    for (int ai = 0; ai < 2; ++ai) {
        #pragma unroll
        for (int ii = 0; ii < 4; ++ii) {
            int r = row0 + ai*64 + (ty<<2) + ii;
            int ix = ai*4 + ii;
            float4 o0, o1;
            o0.x = acc[ix][0] + bb0.x; o0.y = acc[ix][1] + bb0.y;
            o0.z = acc[ix][2] + bb0.z; o0.w = acc[ix][3] + bb0.w;
            o1.x = acc[ix][4] + bb1.x; o1.y = acc[ix][5] + bb1.y;
            o1.z = acc[ix][6] + bb1.z; o1.w = acc[ix][7] + bb1.w;
            *reinterpret_cast<float4*>(C + (size_t)r * DD + col0 + (tx<<2)) = o0;
            *reinterpret_cast<float4*>(C + (size_t)r * DD + col0 + 64 + (tx<<2)) = o1;
        }
    }
}

// ---------------- launch ---------------------------------------------------
extern "C" void kernel_launch(void* const* d_in, const int* in_sizes, int n_in,
                              void* d_out, int out_size)
{
    const float* inputs = (const float*)d_in[0];
    const float* noise  = (const float*)d_in[1];
    const float* mu     = (const float*)d_in[2];
    const float* sigma  = (const float*)d_in[3];
    const float* Wq = (const float*)d_in[4];   const float* bq = (const float*)d_in[5];
    const float* Wk = (const float*)d_in[6];   const float* bk = (const float*)d_in[7];
    const float* Wv = (const float*)d_in[8];   const float* bv = (const float*)d_in[9];
    const float* W1 = (const float*)d_in[10];  const float* b1 = (const float*)d_in[11];
    const float* W2 = (const float*)d_in[12];  const float* b2 = (const float*)d_in[13];
    const float* W_ih = (const float*)d_in[14]; const float* b_ih = (const float*)d_in[15];
    const float* W_hh = (const float*)d_in[16]; const float* b_hh = (const float*)d_in[17];
    const float* gin  = (const float*)d_in[18]; const float* bein = (const float*)d_in[19];
    const float* gsl  = (const float*)d_in[20]; const float* besl = (const float*)d_in[21];
    const float* gff  = (const float*)d_in[22]; const float* beff = (const float*)d_in[23];

    float* out = (float*)d_out;
    float* out_slots = out;
    float* out_attn  = out + NB * 20 * DD;

    float *pk, *pv;
    cudaGetSymbolAddress((void**)&pk, g_k);
    cudaGetSymbolAddress((void**)&pv, g_v);

    // k,v projections for all frames (LN fused), fully parallel
    {
        const int M = NB * NFR * NT;          // 98304
        dim3 grid(DD / 128, M / 128);         // (2, 768)
        kv_gemm<<<grid, 256>>>(inputs, Wk, bk, pk, gin, bein);
        kv_gemm<<<grid, 256>>>(inputs, Wv, bv, pv, gin, bein);
    }

    // serial core: 32 independent per-batch chains, 4-CTA clusters
    persist_kernel<<<128, 256>>>(noise, mu, sigma,
                                 Wq, bq, W1, b1, W2, b2,
                                 W_ih, b_ih, W_hh, b_hh,
                                 gsl, besl, gff, beff,
                                 out_slots, out_attn);
}